// round 7
// baseline (speedup 1.0000x reference)
#include <cuda_runtime.h>
#include <cuda_bf16.h>
#include <cstddef>
#include <cstdint>

// Problem constants (CTCLoss_56298431315981): T=1024, B=32, C=1024, L=128
constexpr int kT = 1024;
constexpr int kB = 32;
constexpr int kC = 1024;
constexpr int kL = 128;
constexpr int kS = 2 * kL + 1;   // 257 extended states
constexpr int kRow = 384;        // floats per (b,t) row: 3 comps x 32 lanes x 4
constexpr int kTP = kT + 24;     // padded T: prefetch never clamps

// Scratch (static __device__ — no allocations allowed)
// Layout: float4 view [b][t][comp 0..2][lane]; lane owns states 10l..10l+9:
// comp0 = p(s0..s0+3), comp1 = p(s0+4..s0+7), comp2 = (p(s0+8), p(s0+9),
// log2(row max), 0).
__device__ float g_E2[(size_t)kB * kTP * kRow];
__device__ float g_nll[kB];

// ---- packed f32x2 ops (Blackwell; PTX-only, ptxas never auto-fuses) -------
__device__ __forceinline__ void add2(float& dl, float& dh,
                                     float al, float ah, float bl, float bh)
{
    asm("{\n\t.reg .b64 A,B,D;\n\t"
        "mov.b64 A,{%2,%3}; mov.b64 B,{%4,%5};\n\t"
        "add.rn.f32x2 D,A,B;\n\t"
        "mov.b64 {%0,%1},D;\n\t}"
        : "=f"(dl), "=f"(dh) : "f"(al), "f"(ah), "f"(bl), "f"(bh));
}
__device__ __forceinline__ void mul2(float& dl, float& dh,
                                     float al, float ah, float bl, float bh)
{
    asm("{\n\t.reg .b64 A,B,D;\n\t"
        "mov.b64 A,{%2,%3}; mov.b64 B,{%4,%5};\n\t"
        "mul.rn.f32x2 D,A,B;\n\t"
        "mov.b64 {%0,%1},D;\n\t}"
        : "=f"(dl), "=f"(dh) : "f"(al), "f"(ah), "f"(bl), "f"(bh));
}
__device__ __forceinline__ void fma2(float& dl, float& dh,
                                     float al, float ah, float bl, float bh,
                                     float cl, float ch)
{
    asm("{\n\t.reg .b64 A,B,C,D;\n\t"
        "mov.b64 A,{%2,%3}; mov.b64 B,{%4,%5}; mov.b64 C,{%6,%7};\n\t"
        "fma.rn.f32x2 D,A,B,C;\n\t"
        "mov.b64 {%0,%1},D;\n\t}"
        : "=f"(dl), "=f"(dh)
        : "f"(al), "f"(ah), "f"(bl), "f"(bh), "f"(cl), "f"(ch));
}

// ---------------------------------------------------------------------------
// 2^d as a product of two representable fp32 powers of two. |d|<=252 exact;
// d<-252 flushes to 0. Factors must stay separate (product can be inf;
// 0 * f1 * f2 must remain 0 for empty-lane halos).
// ---------------------------------------------------------------------------
__device__ __forceinline__ void twoFactor(int d, float& f1, float& f2)
{
    d = max(min(d, 252), -300);
    if (d < -252) { f1 = 0.f; f2 = 0.f; return; }
    const int dh = d / 2;  // trunc toward 0: both halves stay in [-126,126]
    f1 = __int_as_float((dh + 127) << 23);
    f2 = __int_as_float((d - dh + 127) << 23);
}

// ---------------------------------------------------------------------------
// Kernel 1: per-(t,b) softmax; write row-max-normalized linear probabilities,
// 10 states per lane, plus log2(rowmax) in comp2.z. One warp per row.
// t-REVERSED block order: small-t rows are written last -> L2-hot for the DP.
// ---------------------------------------------------------------------------
__global__ void __launch_bounds__(256) ctc_emis_kernel(
    const float* __restrict__ data, const int* __restrict__ labels)
{
    __shared__ float sh[8][kC];
    __shared__ int   shlab[8][kL];
    const int warp = threadIdx.x >> 5;
    const int lane = threadIdx.x & 31;
    const int row  = (kT * kB - 1) - ((blockIdx.x << 3) + warp); // reversed
    const int t = row >> 5;                      // B == 32
    const int b = row & 31;

    reinterpret_cast<int4*>(shlab[warp])[lane] =
        reinterpret_cast<const int4*>(labels + b * kL)[lane];

    const float4* src = reinterpret_cast<const float4*>(data + (size_t)(t * kB + b) * kC);

    float m = -3.4e38f;
    float4 v[8];
#pragma unroll
    for (int i = 0; i < 8; i++) {
        v[i] = src[(i << 5) + lane];
        reinterpret_cast<float4*>(sh[warp])[(i << 5) + lane] = v[i];
        m = fmaxf(m, fmaxf(fmaxf(v[i].x, v[i].y), fmaxf(v[i].z, v[i].w)));
    }
#pragma unroll
    for (int o = 16; o; o >>= 1) m = fmaxf(m, __shfl_xor_sync(0xffffffffu, m, o));

    float ssum = 0.f;
#pragma unroll
    for (int i = 0; i < 8; i++) {
        ssum += __expf(v[i].x - m) + __expf(v[i].y - m) +
                __expf(v[i].z - m) + __expf(v[i].w - m);
    }
#pragma unroll
    for (int o = 16; o; o >>= 1) ssum += __shfl_xor_sync(0xffffffffu, ssum, o);

    const float lse = m + __logf(ssum);

    __syncwarp();  // smem stores (data row + labels) visible warp-wide

    const float blank = __expf(sh[warp][0] - lse);   // class 0 = blank
    float out[10];
#pragma unroll
    for (int j = 0; j < 10; j++) out[j] = 0.f;
    const int s0 = 10 * lane;
    float pmax = 0.f;
#pragma unroll
    for (int j = 0; j < 10; j++) {
        const int s = s0 + j;
        if (s < kS) {
            out[j] = (s & 1) ? __expf(sh[warp][shlab[warp][s >> 1]] - lse) : blank;
            pmax = fmaxf(pmax, out[j]);
        }
    }
#pragma unroll
    for (int o = 16; o; o >>= 1) pmax = fmaxf(pmax, __shfl_xor_sync(0xffffffffu, pmax, o));

    const float r   = __frcp_rn(pmax);
    const float lg2 = -__log2f(r);        // log2 of the factor we divided out
#pragma unroll
    for (int j = 0; j < 10; j++) out[j] *= r;

    float4* dst = reinterpret_cast<float4*>(g_E2 + ((size_t)b * kTP + t) * kRow);
    dst[lane]      = make_float4(out[0], out[1], out[2], out[3]);
    dst[32 + lane] = make_float4(out[4], out[5], out[6], out[7]);
    dst[64 + lane] = make_float4(out[8], out[9], lg2, 0.f);
}

// ---------------------------------------------------------------------------
// Kernel 2: CTC forward DP, linear domain, packed f32x2 recurrence, per-lane
// block floating point with 2-lane frame-gap cap, rescale every 6 steps.
// One warp per batch element; lane l owns states [10l, 10l+10).
// No barriers, no MUFU, no local memory.
// ---------------------------------------------------------------------------
__global__ void __launch_bounds__(32) ctc_dp_kernel(
    const int* __restrict__ labels, const int* __restrict__ llen,
    const int* __restrict__ dlen)
{
    const unsigned FULL = 0xffffffffu;
    const int NEGI = -(1 << 28);
    const int b    = blockIdx.x;
    const int lane = threadIdx.x;

    const int len = llen[b];
    const int Tb  = dlen[b];               // 512..1024
    const float* __restrict__ Eb = g_E2 + (size_t)b * kTP * kRow;
    const int* __restrict__ lab  = labels + b * kL;

    float allow[10];
#pragma unroll
    for (int j = 0; j < 10; j++) {
        const int s = 10 * lane + j;
        bool al = false;
        if (s < kS && (s & 1) && s >= 3) al = (lab[s >> 1] != lab[(s >> 1) - 1]);
        allow[j] = al ? 1.0f : 0.0f;
    }

    float a[10];
#pragma unroll
    for (int j = 0; j < 10; j++) a[j] = 0.f;
    if (lane == 0) {
        a[0] = __ldg(&Eb[0]);    // t=0 state 0 (blank)
        a[1] = __ldg(&Eb[1]);    // t=0 state 1 (label0)
    }
    float lgsum = __ldg(&Eb[64 * 4 + 2]);  // t=0 row log2(pmax) (comp2 lane0 .z)
    int   X   = 0;
    float sD1 = (lane == 0) ? 0.f : 1.f;   // halo frame factor = sD1*sD2 (keep split!)
    float sD2 = (lane == 0) ? 0.f : 1.f;

    // 12-deep emission prefetch ring (rows t=1..12; Tb >= 512 so all valid)
    float4 P[12][3];
#pragma unroll
    for (int q = 0; q < 12; q++) {
        const float4* r = reinterpret_cast<const float4*>(Eb + (size_t)(1 + q) * kRow);
        P[q][0] = __ldg(r + lane);
        P[q][1] = __ldg(r + 32 + lane);
        P[q][2] = __ldg(r + 64 + lane);
    }

    auto dostep = [&](const float4* Pq) {
        float h1 = __shfl_up_sync(FULL, a[9], 1);   // alpha[s0-1] (pred frame)
        float h2 = __shfl_up_sync(FULL, a[8], 1);   // alpha[s0-2] (pred frame)
        mul2(h2, h1, h2, h1, sD1, sD1);             // to local frame (packed)
        mul2(h2, h1, h2, h1, sD2, sD2);
        lgsum += Pq[2].z;                           // row log2(pmax)
        float na[10];
        // pair i covers states (2i, 2i+1): na = (A + S1 + allow*S2) * P
        // S1 = (a[2i-1], a[2i]),  S2 = (a[2i-2], a[2i-1]); a[-1]=h1, a[-2]=h2
        float sl, shh;
        add2(sl, shh, a[0], a[1], h1,   a[0]);
        fma2(sl, shh, allow[0], allow[1], h2,   h1,   sl, shh);
        mul2(na[0], na[1], sl, shh, Pq[0].x, Pq[0].y);

        add2(sl, shh, a[2], a[3], a[1], a[2]);
        fma2(sl, shh, allow[2], allow[3], a[0], a[1], sl, shh);
        mul2(na[2], na[3], sl, shh, Pq[0].z, Pq[0].w);

        add2(sl, shh, a[4], a[5], a[3], a[4]);
        fma2(sl, shh, allow[4], allow[5], a[2], a[3], sl, shh);
        mul2(na[4], na[5], sl, shh, Pq[1].x, Pq[1].y);

        add2(sl, shh, a[6], a[7], a[5], a[6]);
        fma2(sl, shh, allow[6], allow[7], a[4], a[5], sl, shh);
        mul2(na[6], na[7], sl, shh, Pq[1].z, Pq[1].w);

        add2(sl, shh, a[8], a[9], a[7], a[8]);
        fma2(sl, shh, allow[8], allow[9], a[6], a[7], sl, shh);
        mul2(na[8], na[9], sl, shh, Pq[2].x, Pq[2].y);
#pragma unroll
        for (int j = 0; j < 10; j++) a[j] = na[j];
    };

    auto prefetch = [&](float4* Pq, int trow) {
        const float4* r = reinterpret_cast<const float4*>(Eb + (size_t)trow * kRow);
        Pq[0] = __ldg(r + lane);
        Pq[1] = __ldg(r + 32 + lane);
        Pq[2] = __ldg(r + 64 + lane);
    };

    // Rescale with 2-lane frame cap (alignment propagates 2 lanes/rescale;
    // wavefront moves 12 states = 1.2 lanes per 6-step period).
    auto rescale = [&]() {
        float m = a[0];
#pragma unroll
        for (int j = 1; j < 10; j++) m = fmaxf(m, a[j]);
        const bool nz = (m > 0.f);
        const int  e    = nz ? (((__float_as_int(m) >> 23) & 0xff) - 127) : 0;
        const int  cand = nz ? (X + e) : NEGI;
        const int  c1 = __shfl_up_sync(FULL, cand, 1);
        const int  c2 = __shfl_up_sync(FULL, cand, 2);
        int Xn;
        if (lane == 0) {
            Xn = nz ? cand : X;
        } else {
            const int low  = max(c1 - 24, c2 - 48);
            const int ownc = nz ? cand : NEGI;
            Xn = max(ownc, low);
            if (Xn <= NEGI) Xn = X;                // fully empty region: keep
        }
        float f1, f2;
        twoFactor(X - Xn, f1, f2);                 // rescale own values (split-safe)
#pragma unroll
        for (int j = 0; j < 10; j += 2) {
            mul2(a[j], a[j + 1], a[j], a[j + 1], f1, f1);
            mul2(a[j], a[j + 1], a[j], a[j + 1], f2, f2);
        }
        X = Xn;
        const int Xp = __shfl_up_sync(FULL, X, 1); // predecessor FINAL frame
        twoFactor(Xp - X, sD1, sD2);
        if (lane == 0) { sD1 = 0.f; sD2 = 0.f; }
    };

    // Main loop: invariant at head P[i] = emissions(row t+i), i=0..11.
    int t = 1;
    for (; t + 11 < Tb; t += 12) {
        dostep(P[0]);  prefetch(P[0],  t + 12);
        dostep(P[1]);  prefetch(P[1],  t + 13);
        dostep(P[2]);  prefetch(P[2],  t + 14);
        dostep(P[3]);  prefetch(P[3],  t + 15);
        dostep(P[4]);  prefetch(P[4],  t + 16);
        dostep(P[5]);  prefetch(P[5],  t + 17);
        rescale();
        dostep(P[6]);  prefetch(P[6],  t + 18);
        dostep(P[7]);  prefetch(P[7],  t + 19);
        dostep(P[8]);  prefetch(P[8],  t + 20);
        dostep(P[9]);  prefetch(P[9],  t + 21);
        dostep(P[10]); prefetch(P[10], t + 22);
        dostep(P[11]); prefetch(P[11], t + 23);
        rescale();
    }
    // Tail (<=11 steps): STATIC indices only (dynamic indexing of P would
    // demote the whole ring to local memory).
    if (t < Tb) { dostep(P[0]); ++t; }
    if (t < Tb) { dostep(P[1]); ++t; }
    if (t < Tb) { dostep(P[2]); ++t; }
    if (t < Tb) { dostep(P[3]); ++t; }
    rescale();
    if (t < Tb) { dostep(P[4]); ++t; }
    if (t < Tb) { dostep(P[5]); ++t; }
    if (t < Tb) { dostep(P[6]); ++t; }
    if (t < Tb) { dostep(P[7]); ++t; }
    rescale();
    if (t < Tb) { dostep(P[8]); ++t; }
    if (t < Tb) { dostep(P[9]); ++t; }
    if (t < Tb) { dostep(P[10]); ++t; }

    // Final: combine alpha[2*len] and alpha[2*len-1]; add back row log2 sums.
    __shared__ float Af[320];
    __shared__ int   Xf[32];
#pragma unroll
    for (int j = 0; j < 10; j++) Af[10 * lane + j] = a[j];
    Xf[lane] = X;
    __syncwarp();
    if (lane == 0) {
        const int sB = 2 * len, sL = sB - 1;
        const float aB = Af[sB], aL = Af[sL];
        const float yB = (aB > 0.f) ? (log2f(aB) + (float)Xf[sB / 10]) : -1e30f;
        const float yL = (aL > 0.f) ? (log2f(aL) + (float)Xf[sL / 10]) : -1e30f;
        const float mx = fmaxf(yB, yL);
        const float rr = mx + log2f(exp2f(yB - mx) + exp2f(yL - mx)) + lgsum;
        g_nll[b] = -rr * 0.69314718055994530942f;   // log2 -> ln
    }
}

// ---------------------------------------------------------------------------
// Kernel 3: mean over batch -> d_out[0]. Deterministic (no atomics).
// ---------------------------------------------------------------------------
__global__ void ctc_finish_kernel(float* __restrict__ out)
{
    float v = g_nll[threadIdx.x];
#pragma unroll
    for (int o = 16; o; o >>= 1) v += __shfl_xor_sync(0xffffffffu, v, o);
    if (threadIdx.x == 0) out[0] = v * (1.0f / kB);
}

extern "C" void kernel_launch(void* const* d_in, const int* in_sizes, int n_in,
                              void* d_out, int out_size)
{
    const int*   labels       = (const int*)d_in[0];
    const float* data         = (const float*)d_in[1];
    const int*   label_length = (const int*)d_in[2];
    const int*   data_length  = (const int*)d_in[3];
    float*       out          = (float*)d_out;

    ctc_emis_kernel<<<(kT * kB) / 8, 256>>>(data, labels);
    ctc_dp_kernel<<<kB, 32>>>(labels, label_length, data_length);
    ctc_finish_kernel<<<1, 32>>>(out);
}